// round 9
// baseline (speedup 1.0000x reference)
#include <cuda_runtime.h>
#include <cstdint>

// ---------------------------------------------------------------------------
// LatentAttention: B=2, T=2048, C=1024, H=16, Dh=64, L=64
//   qc = x @ Wqc + bqc        (Wqc = Wq folded with per-head Wc)
//   k  = x @ Wk  + bk ; v = x @ Wv + bv
//   y  = causal-softmax(qc k^T / 8) v      (flash, per (b,h))
//   out = y @ Wo + bo
// This round: packed fp32x2 FMA (fma.rn.f32x2) in both hot inner loops.
// ---------------------------------------------------------------------------

#define BDIM 2
#define TDIM 2048
#define CDIM 1024
#define HN   16
#define LDIM 64
#define MROWS (BDIM*TDIM)   // 4096
#define NEG_INF_F (__int_as_float(0xff800000))

typedef unsigned long long u64;

// d = a*b + d, componentwise on packed {f32,f32}
__device__ __forceinline__ void ffma2(u64& d, u64 a, u64 b) {
    asm("fma.rn.f32x2 %0, %1, %2, %0;" : "+l"(d) : "l"(a), "l"(b));
}
__device__ __forceinline__ u64 mul2(u64 a, u64 b) {
    u64 r; asm("mul.rn.f32x2 %0, %1, %2;" : "=l"(r) : "l"(a), "l"(b)); return r;
}
__device__ __forceinline__ u64 splat2(float x) {
    u64 r; unsigned xi = __float_as_uint(x);
    asm("mov.b64 %0, {%1, %1};" : "=l"(r) : "r"(xi));
    return r;
}
__device__ __forceinline__ void unpack2(u64 v, float& lo, float& hi) {
    unsigned a, b;
    asm("mov.b64 {%0, %1}, %2;" : "=r"(a), "=r"(b) : "l"(v));
    lo = __uint_as_float(a); hi = __uint_as_float(b);
}

// scratch (no cudaMalloc allowed)
__device__ float g_Wqc[CDIM*CDIM];
__device__ float g_bqc[CDIM];
__device__ float g_qc[MROWS*CDIM];
__device__ float g_k [MROWS*CDIM];
__device__ float g_v [MROWS*CDIM];
__device__ float g_y [MROWS*CDIM];

// ---------------------------------------------------------------------------
__global__ __launch_bounds__(256) void prep_wqc(const float* __restrict__ Wq,
                                                const float* __restrict__ Wc) {
    __shared__ float Wcs[64*64];
    const int tid = threadIdx.x;
    for (int i = tid; i < 64*64; i += 256) Wcs[i] = Wc[i];
    __syncthreads();
    const int gid = blockIdx.x * 256 + tid;
    const int c   = gid >> 10;
    const int col = gid & 1023;
    const int h   = col >> 6;
    const int l   = col & 63;
    const float* wrow = Wq + c*CDIM + h*64;
    float acc = 0.f;
#pragma unroll
    for (int d = 0; d < 64; d++) acc += wrow[d] * Wcs[d*64 + l];
    g_Wqc[gid] = acc;
}

__global__ void prep_bqc(const float* __restrict__ bq,
                         const float* __restrict__ Wc) {
    const int col = blockIdx.x * blockDim.x + threadIdx.x;
    const int h = col >> 6, l = col & 63;
    float acc = 0.f;
#pragma unroll
    for (int d = 0; d < 64; d++) acc += bq[h*64 + d] * Wc[d*64 + l];
    g_bqc[col] = acc;
}

// ---------------------------------------------------------------------------
// SGEMM with f32x2 inner product. 128x128 tile, BK=8, 8x8/thread (as 8x4 pairs).
// ---------------------------------------------------------------------------
__global__ __launch_bounds__(256) void sgemm_bias(
    const float* __restrict__ A, const float* __restrict__ B,
    const float* __restrict__ bias, float* __restrict__ C,
    int M, int N, int K)
{
    __shared__ float As[8][128];
    __shared__ float Bs[8][128];

    const int tid  = threadIdx.x;
    const int brow = blockIdx.y * 128;
    const int bcol = blockIdx.x * 128;

    const int aRow = tid >> 1;            // 0..127
    const int aCol = (tid & 1) << 2;      // 0 or 4
    const int bRow = tid >> 5;            // 0..7
    const int bCol = (tid & 31) << 2;     // 0..124

    const int ty = tid >> 4;              // 0..15
    const int tx = tid & 15;              // 0..15

    const float* Aptr = A + (size_t)(brow + aRow) * K + aCol;
    const float* Bptr = B + (size_t)bRow * N + bcol + bCol;

    u64 acc2[8][4];
#pragma unroll
    for (int i = 0; i < 8; i++)
#pragma unroll
        for (int j = 0; j < 4; j++) acc2[i][j] = 0ull;

    float4 a_pf = *(const float4*)(Aptr);
    float4 b_pf = *(const float4*)(Bptr);

    for (int k0 = 0; k0 < K; k0 += 8) {
        As[aCol+0][aRow] = a_pf.x;
        As[aCol+1][aRow] = a_pf.y;
        As[aCol+2][aRow] = a_pf.z;
        As[aCol+3][aRow] = a_pf.w;
        *(float4*)(&Bs[bRow][bCol]) = b_pf;
        __syncthreads();

        if (k0 + 8 < K) {
            a_pf = *(const float4*)(Aptr + k0 + 8);
            b_pf = *(const float4*)(Bptr + (size_t)(k0 + 8) * N);
        }

#pragma unroll
        for (int kk = 0; kk < 8; kk++) {
            float4 a0 = *(const float4*)(&As[kk][ty*8]);
            float4 a1 = *(const float4*)(&As[kk][ty*8 + 4]);
            ulonglong2 bp0 = *(const ulonglong2*)(&Bs[kk][tx*8]);
            ulonglong2 bp1 = *(const ulonglong2*)(&Bs[kk][tx*8 + 4]);
            const u64 bn[4] = {bp0.x, bp0.y, bp1.x, bp1.y};
            const float am[8] = {a0.x, a0.y, a0.z, a0.w,
                                 a1.x, a1.y, a1.z, a1.w};
#pragma unroll
            for (int i = 0; i < 8; i++) {
                const u64 a2 = splat2(am[i]);
#pragma unroll
                for (int j = 0; j < 4; j++) ffma2(acc2[i][j], a2, bn[j]);
            }
        }
        __syncthreads();
    }

    float bterm[8];
#pragma unroll
    for (int j = 0; j < 8; j++) bterm[j] = bias[bcol + tx*8 + j];

#pragma unroll
    for (int i = 0; i < 8; i++) {
        float c[8];
#pragma unroll
        for (int j = 0; j < 4; j++) unpack2(acc2[i][j], c[2*j], c[2*j+1]);
        float* crow = C + (size_t)(brow + ty*8 + i) * N + bcol + tx*8;
        *(float4*)(crow)     = make_float4(c[0]+bterm[0], c[1]+bterm[1],
                                           c[2]+bterm[2], c[3]+bterm[3]);
        *(float4*)(crow + 4) = make_float4(c[4]+bterm[4], c[5]+bterm[5],
                                           c[6]+bterm[6], c[7]+bterm[7]);
    }
}

// ---------------------------------------------------------------------------
// Flash attention, fp32x2, register-blocked. 128-row Q tile, 64 K/V tile.
// 256 threads as 32(ty) x 8(tx); each thread: S/O[4 rows][8 cols] = [4][4] pairs.
// ---------------------------------------------------------------------------
#define QT_S 132
#define KT_S 72
#define VS_S 72
#define P_S  68
#define FLASH_SMEM ((64*QT_S + 64*KT_S + 64*VS_S + 128*P_S) * 4)

__global__ __launch_bounds__(256, 2) void flash_attn(
    const float* __restrict__ Q, const float* __restrict__ K,
    const float* __restrict__ V, float* __restrict__ Y)
{
    extern __shared__ float sm[];
    float* QT = sm;                  // [64][QT_S]
    float* KT = QT + 64*QT_S;        // [64][KT_S]
    float* Vs = KT + 64*KT_S;        // [64][VS_S]
    float* P  = Vs + 64*VS_S;        // [128][P_S]

    const int tid = threadIdx.x;
    const int qt  = (gridDim.x - 1) - blockIdx.x;   // heavy tiles first
    const int bh  = blockIdx.y;
    const int b   = bh >> 4;
    const int h   = bh & 15;
    const int ty  = tid >> 3;             // 0..31
    const int tx  = tid & 7;              // 0..7
    const int r0  = ty << 2;
    const int c0  = tx << 3;

    const size_t base = ((size_t)b * TDIM) * CDIM + h * 64;

    // load Q tile transposed: QT[d][row]
    for (int i = tid; i < 128*16; i += 256) {
        const int row = i >> 4;
        const int d4  = (i & 15) << 2;
        float4 q4 = *(const float4*)(Q + base + (size_t)(qt*128 + row)*CDIM + d4);
        QT[(d4+0)*QT_S + row] = q4.x;
        QT[(d4+1)*QT_S + row] = q4.y;
        QT[(d4+2)*QT_S + row] = q4.z;
        QT[(d4+3)*QT_S + row] = q4.w;
    }

    u64 o2[4][4];
#pragma unroll
    for (int i = 0; i < 4; i++)
#pragma unroll
        for (int j = 0; j < 4; j++) o2[i][j] = 0ull;
    float m[4], l[4];
#pragma unroll
    for (int i = 0; i < 4; i++) { m[i] = NEG_INF_F; l[i] = 0.f; }

    const int kt_end = 2*qt + 1;
    for (int kt = 0; kt <= kt_end; kt++) {
        __syncthreads();

        for (int i = tid; i < 64*16; i += 256) {
            const int row = i >> 4;
            const int d4  = (i & 15) << 2;
            const size_t goff = base + (size_t)(kt*64 + row)*CDIM + d4;
            float4 k4 = *(const float4*)(K + goff);
            KT[(d4+0)*KT_S + row] = k4.x;
            KT[(d4+1)*KT_S + row] = k4.y;
            KT[(d4+2)*KT_S + row] = k4.z;
            KT[(d4+3)*KT_S + row] = k4.w;
            *(float4*)(&Vs[row*VS_S + d4]) = *(const float4*)(V + goff);
        }
        __syncthreads();

        // S = Q.K^T in packed pairs
        u64 s2[4][4];
#pragma unroll
        for (int i = 0; i < 4; i++)
#pragma unroll
            for (int j = 0; j < 4; j++) s2[i][j] = 0ull;

#pragma unroll 2
        for (int d = 0; d < 64; d++) {
            float4 q4 = *(const float4*)(&QT[d*QT_S + r0]);
            ulonglong2 kp0 = *(const ulonglong2*)(&KT[d*KT_S + c0]);
            ulonglong2 kp1 = *(const ulonglong2*)(&KT[d*KT_S + c0 + 4]);
            const u64 kc2[4] = {kp0.x, kp0.y, kp1.x, kp1.y};
            const float qr[4] = {q4.x, q4.y, q4.z, q4.w};
#pragma unroll
            for (int i = 0; i < 4; i++) {
                const u64 q2 = splat2(qr[i]);
#pragma unroll
                for (int j = 0; j < 4; j++) ffma2(s2[i][j], q2, kc2[j]);
            }
        }

        // unpack, scale, mask
        float s[4][8];
#pragma unroll
        for (int i = 0; i < 4; i++)
#pragma unroll
            for (int j = 0; j < 4; j++) unpack2(s2[i][j], s[i][2*j], s[i][2*j+1]);

        const float scale = 0.125f;
        if (kt >= 2*qt) {
#pragma unroll
            for (int i = 0; i < 4; i++) {
                const int grow = qt*128 + r0 + i;
#pragma unroll
                for (int j = 0; j < 8; j++) {
                    const int gcol = kt*64 + c0 + j;
                    s[i][j] = (gcol > grow) ? NEG_INF_F : s[i][j] * scale;
                }
            }
        } else {
#pragma unroll
            for (int i = 0; i < 4; i++)
#pragma unroll
                for (int j = 0; j < 8; j++) s[i][j] *= scale;
        }

        // online softmax per row (8 tx lanes = low 3 lane bits)
#pragma unroll
        for (int i = 0; i < 4; i++) {
            float rmax = s[i][0];
#pragma unroll
            for (int j = 1; j < 8; j++) rmax = fmaxf(rmax, s[i][j]);
            rmax = fmaxf(rmax, __shfl_xor_sync(0xffffffffu, rmax, 1));
            rmax = fmaxf(rmax, __shfl_xor_sync(0xffffffffu, rmax, 2));
            rmax = fmaxf(rmax, __shfl_xor_sync(0xffffffffu, rmax, 4));

            const float mnew = fmaxf(m[i], rmax);
            const float corr = __expf(m[i] - mnew);
            float psum = 0.f;
#pragma unroll
            for (int j = 0; j < 8; j++) {
                const float p = __expf(s[i][j] - mnew);
                s[i][j] = p;
                psum += p;
            }
            psum += __shfl_xor_sync(0xffffffffu, psum, 1);
            psum += __shfl_xor_sync(0xffffffffu, psum, 2);
            psum += __shfl_xor_sync(0xffffffffu, psum, 4);
            l[i] = l[i] * corr + psum;
            m[i] = mnew;

            const u64 corr2 = splat2(corr);
#pragma unroll
            for (int j = 0; j < 4; j++) o2[i][j] = mul2(o2[i][j], corr2);

            *(float4*)(&P[(r0+i)*P_S + c0])     =
                make_float4(s[i][0], s[i][1], s[i][2], s[i][3]);
            *(float4*)(&P[(r0+i)*P_S + c0 + 4]) =
                make_float4(s[i][4], s[i][5], s[i][6], s[i][7]);
        }
        __syncthreads();

        // O += P @ V in packed pairs
#pragma unroll 2
        for (int kk0 = 0; kk0 < 64; kk0 += 4) {
            float4 pr[4];
#pragma unroll
            for (int i = 0; i < 4; i++)
                pr[i] = *(const float4*)(&P[(r0+i)*P_S + kk0]);
#pragma unroll
            for (int t = 0; t < 4; t++) {
                const int kk = kk0 + t;
                ulonglong2 vp0 = *(const ulonglong2*)(&Vs[kk*VS_S + c0]);
                ulonglong2 vp1 = *(const ulonglong2*)(&Vs[kk*VS_S + c0 + 4]);
                const u64 vv2[4] = {vp0.x, vp0.y, vp1.x, vp1.y};
                const float pv[4] = {
                    t == 0 ? pr[0].x : t == 1 ? pr[0].y : t == 2 ? pr[0].z : pr[0].w,
                    t == 0 ? pr[1].x : t == 1 ? pr[1].y : t == 2 ? pr[1].z : pr[1].w,
                    t == 0 ? pr[2].x : t == 1 ? pr[2].y : t == 2 ? pr[2].z : pr[2].w,
                    t == 0 ? pr[3].x : t == 1 ? pr[3].y : t == 2 ? pr[3].z : pr[3].w};
#pragma unroll
                for (int i = 0; i < 4; i++) {
                    const u64 p2 = splat2(pv[i]);
#pragma unroll
                    for (int j = 0; j < 4; j++) ffma2(o2[i][j], p2, vv2[j]);
                }
            }
        }
    }

#pragma unroll
    for (int i = 0; i < 4; i++) {
        const u64 inv2 = splat2(1.f / l[i]);
        float* yp = Y + base + (size_t)(qt*128 + r0 + i)*CDIM + c0;
        ulonglong2 y0, y1;
        y0.x = mul2(o2[i][0], inv2);
        y0.y = mul2(o2[i][1], inv2);
        y1.x = mul2(o2[i][2], inv2);
        y1.y = mul2(o2[i][3], inv2);
        *(ulonglong2*)(yp)     = y0;
        *(ulonglong2*)(yp + 4) = y1;
    }
}

// ---------------------------------------------------------------------------
extern "C" void kernel_launch(void* const* d_in, const int* in_sizes, int n_in,
                              void* d_out, int out_size) {
    const float* x  = (const float*)d_in[0];
    const float* Wq = (const float*)d_in[1];
    const float* bq = (const float*)d_in[2];
    const float* Wk = (const float*)d_in[3];
    const float* bk = (const float*)d_in[4];
    const float* Wv = (const float*)d_in[5];
    const float* bv = (const float*)d_in[6];
    const float* Wo = (const float*)d_in[7];
    const float* bo = (const float*)d_in[8];
    const float* Wc = (const float*)d_in[9];
    float* out = (float*)d_out;

    float *wqc, *bqc, *qc, *kb, *vb, *yb;
    cudaGetSymbolAddress((void**)&wqc, g_Wqc);
    cudaGetSymbolAddress((void**)&bqc, g_bqc);
    cudaGetSymbolAddress((void**)&qc,  g_qc);
    cudaGetSymbolAddress((void**)&kb,  g_k);
    cudaGetSymbolAddress((void**)&vb,  g_v);
    cudaGetSymbolAddress((void**)&yb,  g_y);

    cudaFuncSetAttribute(flash_attn,
                         cudaFuncAttributeMaxDynamicSharedMemorySize,
                         FLASH_SMEM);

    prep_wqc<<<(CDIM*CDIM)/256, 256>>>(Wq, Wc);
    prep_bqc<<<CDIM/256, 256>>>(bq, Wc);

    dim3 gg(CDIM/128, MROWS/128);   // (8, 32)
    sgemm_bias<<<gg, 256>>>(x, wqc, bqc, qc, MROWS, CDIM, CDIM);
    sgemm_bias<<<gg, 256>>>(x, Wk,  bk,  kb, MROWS, CDIM, CDIM);
    sgemm_bias<<<gg, 256>>>(x, Wv,  bv,  vb, MROWS, CDIM, CDIM);

    flash_attn<<<dim3(TDIM/128, BDIM*HN), 256, FLASH_SMEM>>>(qc, kb, vb, yb);

    sgemm_bias<<<gg, 256>>>(yb, Wo, bo, out, MROWS, CDIM, CDIM);
}

// round 12
// speedup vs baseline: 1.3685x; 1.3685x over previous
#include <cuda_runtime.h>
#include <cuda_bf16.h>
#include <cstdint>

// ---------------------------------------------------------------------------
// LatentAttention: B=2, T=2048, C=1024, H=16, Dh=64, L=64
// Projections via bf16-split tensor-core GEMM (mma.sync m16n8k16, 3 terms).
// Flash attention: fp32 register-blocked (R8, known good).
// ---------------------------------------------------------------------------

#define BDIM 2
#define TDIM 2048
#define CDIM 1024
#define HN   16
#define MROWS (BDIM*TDIM)   // 4096
#define NEG_INF_F (__int_as_float(0xff800000))

typedef __nv_bfloat16 bf16;

// scratch (no cudaMalloc allowed)
__device__ bf16 g_WqcT_hi[CDIM*CDIM];
__device__ bf16 g_WqcT_lo[CDIM*CDIM];
__device__ bf16 g_WkT_hi [CDIM*CDIM];
__device__ bf16 g_WkT_lo [CDIM*CDIM];
__device__ bf16 g_WvT_hi [CDIM*CDIM];
__device__ bf16 g_WvT_lo [CDIM*CDIM];
__device__ bf16 g_WoT_hi [CDIM*CDIM];
__device__ bf16 g_WoT_lo [CDIM*CDIM];
__device__ bf16 g_xhi[MROWS*CDIM];
__device__ bf16 g_xlo[MROWS*CDIM];
__device__ bf16 g_yhi[MROWS*CDIM];
__device__ bf16 g_ylo[MROWS*CDIM];
__device__ float g_bqc[CDIM];
__device__ float g_qc[MROWS*CDIM];
__device__ float g_k [MROWS*CDIM];
__device__ float g_v [MROWS*CDIM];
__device__ float g_y [MROWS*CDIM];

__device__ __forceinline__ void bsplit(float a, bf16& h, bf16& l) {
    h = __float2bfloat16(a);
    l = __float2bfloat16(a - __bfloat162float(h));
}

// ---------------------------------------------------------------------------
// prep: Wqc = Wq(folded with Wc), stored TRANSPOSED [n][k] as bf16 hi/lo
// ---------------------------------------------------------------------------
__global__ __launch_bounds__(256) void prep_wqc(const float* __restrict__ Wq,
                                                const float* __restrict__ Wc) {
    __shared__ float Wcs[64*64];
    const int tid = threadIdx.x;
    for (int i = tid; i < 64*64; i += 256) Wcs[i] = Wc[i];
    __syncthreads();
    const int gid = blockIdx.x * 256 + tid;
    const int c   = gid >> 10;          // k index (input channel)
    const int col = gid & 1023;         // n index
    const int h   = col >> 6;
    const int l   = col & 63;
    const float* wrow = Wq + c*CDIM + h*64;
    float acc = 0.f;
#pragma unroll
    for (int d = 0; d < 64; d++) acc += wrow[d] * Wcs[d*64 + l];
    bf16 hi, lo; bsplit(acc, hi, lo);
    g_WqcT_hi[col*CDIM + c] = hi;
    g_WqcT_lo[col*CDIM + c] = lo;
}

__global__ void prep_bqc(const float* __restrict__ bq,
                         const float* __restrict__ Wc) {
    const int col = blockIdx.x * blockDim.x + threadIdx.x;
    const int h = col >> 6, l = col & 63;
    float acc = 0.f;
#pragma unroll
    for (int d = 0; d < 64; d++) acc += bq[h*64 + d] * Wc[d*64 + l];
    g_bqc[col] = acc;
}

// W[k][n] fp32 -> WT[n][k] bf16 hi/lo
__global__ __launch_bounds__(256) void conv_wT(const float* __restrict__ W,
                                               bf16* __restrict__ hiT,
                                               bf16* __restrict__ loT) {
    const int i = blockIdx.x * 256 + threadIdx.x;   // 0..1M-1
    const int k = i >> 10, n = i & 1023;
    bf16 h, l; bsplit(W[i], h, l);
    hiT[n*CDIM + k] = h;
    loT[n*CDIM + k] = l;
}

// row-major fp32 -> bf16 hi/lo (same layout)
__global__ __launch_bounds__(256) void conv_split(const float* __restrict__ src,
                                                  bf16* __restrict__ hi,
                                                  bf16* __restrict__ lo) {
    const int i = blockIdx.x * 256 + threadIdx.x;
    bf16 h, l; bsplit(src[i], h, l);
    hi[i] = h; lo[i] = l;
}

// ---------------------------------------------------------------------------
// Tensor-core GEMM: C[M,1024] = A[M,1024] @ B^T(stored [n][k]) + bias
// A given as bf16 hi/lo row-major; B as bf16 hi/lo [n][k].
// 3-term split accumulate in fp32. Block 128x128, BK=64, 8 warps (2m x 4n),
// warp tile 64x32 via m16n8k16.
// ---------------------------------------------------------------------------
#define TCPIT 72
#define TC_SMEM (4*128*TCPIT*2)   // 73728 B

__device__ __forceinline__ void mma16816(float* c, const unsigned* a,
                                         const unsigned* b) {
    asm volatile(
        "mma.sync.aligned.m16n8k16.row.col.f32.bf16.bf16.f32 "
        "{%0,%1,%2,%3}, {%4,%5,%6,%7}, {%8,%9}, {%0,%1,%2,%3};"
        : "+f"(c[0]), "+f"(c[1]), "+f"(c[2]), "+f"(c[3])
        : "r"(a[0]), "r"(a[1]), "r"(a[2]), "r"(a[3]), "r"(b[0]), "r"(b[1]));
}

__global__ __launch_bounds__(256, 1) void sgemm_tc(
    const bf16* __restrict__ Ahi, const bf16* __restrict__ Alo,
    const bf16* __restrict__ Bhi, const bf16* __restrict__ Blo,
    const float* __restrict__ bias, float* __restrict__ C)
{
    extern __shared__ __align__(16) char smraw[];
    bf16* As_hi = (bf16*)smraw;                 // [128][TCPIT]
    bf16* As_lo = As_hi + 128*TCPIT;
    bf16* Bs_hi = As_lo + 128*TCPIT;            // [128][TCPIT] (n-major)
    bf16* Bs_lo = Bs_hi + 128*TCPIT;

    const int tid  = threadIdx.x;
    const int brow = blockIdx.y * 128;
    const int bcol = blockIdx.x * 128;
    const int w    = tid >> 5;
    const int lane = tid & 31;
    const int g    = lane >> 2;          // 0..7
    const int tg   = lane & 3;           // 0..3
    const int wm   = (w >> 2) * 64;      // 0 or 64
    const int wn   = (w & 3) * 32;       // 0,32,64,96

    float c[4][4][4];
#pragma unroll
    for (int i = 0; i < 4; i++)
#pragma unroll
        for (int j = 0; j < 4; j++)
#pragma unroll
            for (int t = 0; t < 4; t++) c[i][j][t] = 0.f;

    for (int kc = 0; kc < CDIM; kc += 64) {
        __syncthreads();
        // load A tile (rows brow..+127, cols kc..+63) and B tile (rows bcol..)
#pragma unroll
        for (int u = tid; u < 128*8; u += 256) {
            const int r  = u >> 3;
            const int c8 = (u & 7) << 3;
            const size_t ga = (size_t)(brow + r) * CDIM + kc + c8;
            const size_t gb = (size_t)(bcol + r) * CDIM + kc + c8;
            *(uint4*)(&As_hi[r*TCPIT + c8]) = *(const uint4*)(&Ahi[ga]);
            *(uint4*)(&As_lo[r*TCPIT + c8]) = *(const uint4*)(&Alo[ga]);
            *(uint4*)(&Bs_hi[r*TCPIT + c8]) = *(const uint4*)(&Bhi[gb]);
            *(uint4*)(&Bs_lo[r*TCPIT + c8]) = *(const uint4*)(&Blo[gb]);
        }
        __syncthreads();

#pragma unroll
        for (int ks = 0; ks < 4; ks++) {
            const int kb = ks*16 + 2*tg;
            unsigned bh[4][2], bl[4][2];
#pragma unroll
            for (int j = 0; j < 4; j++) {
                const int rb = (wn + 8*j + g)*TCPIT + kb;
                bh[j][0] = *(const unsigned*)(&Bs_hi[rb]);
                bh[j][1] = *(const unsigned*)(&Bs_hi[rb + 8]);
                bl[j][0] = *(const unsigned*)(&Bs_lo[rb]);
                bl[j][1] = *(const unsigned*)(&Bs_lo[rb + 8]);
            }
#pragma unroll
            for (int i = 0; i < 4; i++) {
                const int ra = (wm + 16*i + g)*TCPIT + kb;
                unsigned ah[4], al[4];
                ah[0] = *(const unsigned*)(&As_hi[ra]);
                ah[1] = *(const unsigned*)(&As_hi[ra + 8*TCPIT]);
                ah[2] = *(const unsigned*)(&As_hi[ra + 8]);
                ah[3] = *(const unsigned*)(&As_hi[ra + 8*TCPIT + 8]);
                al[0] = *(const unsigned*)(&As_lo[ra]);
                al[1] = *(const unsigned*)(&As_lo[ra + 8*TCPIT]);
                al[2] = *(const unsigned*)(&As_lo[ra + 8]);
                al[3] = *(const unsigned*)(&As_lo[ra + 8*TCPIT + 8]);
#pragma unroll
                for (int j = 0; j < 4; j++) {
                    mma16816(c[i][j], ah, bh[j]);   // hi*hi
                    mma16816(c[i][j], ah, bl[j]);   // hi*lo
                    mma16816(c[i][j], al, bh[j]);   // lo*hi
                }
            }
        }
    }

    // epilogue: add bias, write fp32
#pragma unroll
    for (int j = 0; j < 4; j++) {
        const int gc = bcol + wn + 8*j + 2*tg;
        const float2 b2 = *(const float2*)(&bias[gc]);
#pragma unroll
        for (int i = 0; i < 4; i++) {
            const int gr = brow + wm + 16*i + g;
            float2 s0 = make_float2(c[i][j][0] + b2.x, c[i][j][1] + b2.y);
            float2 s1 = make_float2(c[i][j][2] + b2.x, c[i][j][3] + b2.y);
            *(float2*)(&C[(size_t)gr*CDIM + gc])       = s0;
            *(float2*)(&C[(size_t)(gr+8)*CDIM + gc])   = s1;
        }
    }
}

// ---------------------------------------------------------------------------
// Flash attention, fp32, register-blocked (R8 version, known good).
// ---------------------------------------------------------------------------
#define QT_S 132
#define KT_S 72
#define VS_S 72
#define P_S  68
#define FLASH_SMEM ((64*QT_S + 64*KT_S + 64*VS_S + 128*P_S) * 4)

__global__ __launch_bounds__(256, 2) void flash_attn(
    const float* __restrict__ Q, const float* __restrict__ K,
    const float* __restrict__ V, float* __restrict__ Y)
{
    extern __shared__ float sm[];
    float* QT = sm;                  // [64][QT_S]
    float* KT = QT + 64*QT_S;        // [64][KT_S]
    float* Vs = KT + 64*KT_S;        // [64][VS_S]
    float* P  = Vs + 64*VS_S;        // [128][P_S]

    const int tid = threadIdx.x;
    const int qt  = (gridDim.x - 1) - blockIdx.x;
    const int bh  = blockIdx.y;
    const int b   = bh >> 4;
    const int h   = bh & 15;
    const int ty  = tid >> 3;
    const int tx  = tid & 7;
    const int r0  = ty << 2;
    const int c0  = tx << 3;

    const size_t base = ((size_t)b * TDIM) * CDIM + h * 64;

    for (int i = tid; i < 128*16; i += 256) {
        const int row = i >> 4;
        const int d4  = (i & 15) << 2;
        float4 q4 = *(const float4*)(Q + base + (size_t)(qt*128 + row)*CDIM + d4);
        QT[(d4+0)*QT_S + row] = q4.x;
        QT[(d4+1)*QT_S + row] = q4.y;
        QT[(d4+2)*QT_S + row] = q4.z;
        QT[(d4+3)*QT_S + row] = q4.w;
    }

    float o[4][8];
#pragma unroll
    for (int i = 0; i < 4; i++)
#pragma unroll
        for (int j = 0; j < 8; j++) o[i][j] = 0.f;
    float m[4], l[4];
#pragma unroll
    for (int i = 0; i < 4; i++) { m[i] = NEG_INF_F; l[i] = 0.f; }

    const int kt_end = 2*qt + 1;
    for (int kt = 0; kt <= kt_end; kt++) {
        __syncthreads();

        for (int i = tid; i < 64*16; i += 256) {
            const int row = i >> 4;
            const int d4  = (i & 15) << 2;
            const size_t goff = base + (size_t)(kt*64 + row)*CDIM + d4;
            float4 k4 = *(const float4*)(K + goff);
            KT[(d4+0)*KT_S + row] = k4.x;
            KT[(d4+1)*KT_S + row] = k4.y;
            KT[(d4+2)*KT_S + row] = k4.z;
            KT[(d4+3)*KT_S + row] = k4.w;
            *(float4*)(&Vs[row*VS_S + d4]) = *(const float4*)(V + goff);
        }
        __syncthreads();

        float s[4][8];
#pragma unroll
        for (int i = 0; i < 4; i++)
#pragma unroll
            for (int j = 0; j < 8; j++) s[i][j] = 0.f;

#pragma unroll 2
        for (int d = 0; d < 64; d++) {
            float4 q4 = *(const float4*)(&QT[d*QT_S + r0]);
            float4 k0v = *(const float4*)(&KT[d*KT_S + c0]);
            float4 k1v = *(const float4*)(&KT[d*KT_S + c0 + 4]);
            const float qr[4] = {q4.x, q4.y, q4.z, q4.w};
            const float kc[8] = {k0v.x, k0v.y, k0v.z, k0v.w,
                                 k1v.x, k1v.y, k1v.z, k1v.w};
#pragma unroll
            for (int i = 0; i < 4; i++)
#pragma unroll
                for (int j = 0; j < 8; j++) s[i][j] += qr[i] * kc[j];
        }

        const float scale = 0.125f;
        if (kt >= 2*qt) {
#pragma unroll
            for (int i = 0; i < 4; i++) {
                const int grow = qt*128 + r0 + i;
#pragma unroll
                for (int j = 0; j < 8; j++) {
                    const int gcol = kt*64 + c0 + j;
                    s[i][j] = (gcol > grow) ? NEG_INF_F : s[i][j] * scale;
                }
            }
        } else {
#pragma unroll
            for (int i = 0; i < 4; i++)
#pragma unroll
                for (int j = 0; j < 8; j++) s[i][j] *= scale;
        }

#pragma unroll
        for (int i = 0; i < 4; i++) {
            float rmax = s[i][0];
#pragma unroll
            for (int j = 1; j < 8; j++) rmax = fmaxf(rmax, s[i][j]);
            rmax = fmaxf(rmax, __shfl_xor_sync(0xffffffffu, rmax, 1));
            rmax = fmaxf(rmax, __shfl_xor_sync(0xffffffffu, rmax, 2));
            rmax = fmaxf(rmax, __shfl_xor_sync(0xffffffffu, rmax, 4));

            const float mnew = fmaxf(m[i], rmax);
            const float corr = __expf(m[i] - mnew);
            float psum = 0.f;
#pragma unroll
            for (int j = 0; j < 8; j++) {
                const float p = __expf(s[i][j] - mnew);
                s[i][j] = p;
                psum += p;
            }
            psum += __shfl_xor_sync(0xffffffffu, psum, 1);
            psum += __shfl_xor_sync(0xffffffffu, psum, 2);
            psum += __shfl_xor_sync(0xffffffffu, psum, 4);
            l[i] = l[i] * corr + psum;
            m[i] = mnew;
#pragma unroll
            for (int j = 0; j < 8; j++) o[i][j] *= corr;

            *(float4*)(&P[(r0+i)*P_S + c0])     =
                make_float4(s[i][0], s[i][1], s[i][2], s[i][3]);
            *(float4*)(&P[(r0+i)*P_S + c0 + 4]) =
                make_float4(s[i][4], s[i][5], s[i][6], s[i][7]);
        }
        __syncthreads();

#pragma unroll 2
        for (int kk0 = 0; kk0 < 64; kk0 += 4) {
            float4 pr[4];
#pragma unroll
            for (int i = 0; i < 4; i++)
                pr[i] = *(const float4*)(&P[(r0+i)*P_S + kk0]);
#pragma unroll
            for (int t = 0; t < 4; t++) {
                const int kk = kk0 + t;
                float4 v0 = *(const float4*)(&Vs[kk*VS_S + c0]);
                float4 v1 = *(const float4*)(&Vs[kk*VS_S + c0 + 4]);
                const float vv[8] = {v0.x, v0.y, v0.z, v0.w,
                                     v1.x, v1.y, v1.z, v1.w};
                const float pv[4] = {
                    t == 0 ? pr[0].x : t == 1 ? pr[0].y : t == 2 ? pr[0].z : pr[0].w,
                    t == 0 ? pr[1].x : t == 1 ? pr[1].y : t == 2 ? pr[1].z : pr[1].w,
                    t == 0 ? pr[2].x : t == 1 ? pr[2].y : t == 2 ? pr[2].z : pr[2].w,
                    t == 0 ? pr[3].x : t == 1 ? pr[3].y : t == 2 ? pr[3].z : pr[3].w};
#pragma unroll
                for (int i = 0; i < 4; i++)
#pragma unroll
                    for (int j = 0; j < 8; j++) o[i][j] += pv[i] * vv[j];
            }
        }
    }

#pragma unroll
    for (int i = 0; i < 4; i++) {
        const float inv = 1.f / l[i];
        float* yp = Y + base + (size_t)(qt*128 + r0 + i)*CDIM + c0;
        *(float4*)(yp)     = make_float4(o[i][0]*inv, o[i][1]*inv,
                                         o[i][2]*inv, o[i][3]*inv);
        *(float4*)(yp + 4) = make_float4(o[i][4]*inv, o[i][5]*inv,
                                         o[i][6]*inv, o[i][7]*inv);
    }
}

// ---------------------------------------------------------------------------
extern "C" void kernel_launch(void* const* d_in, const int* in_sizes, int n_in,
                              void* d_out, int out_size) {
    const float* x  = (const float*)d_in[0];
    const float* Wq = (const float*)d_in[1];
    const float* bq = (const float*)d_in[2];
    const float* Wk = (const float*)d_in[3];
    const float* bk = (const float*)d_in[4];
    const float* Wv = (const float*)d_in[5];
    const float* bv = (const float*)d_in[6];
    const float* Wo = (const float*)d_in[7];
    const float* bo = (const float*)d_in[8];
    const float* Wc = (const float*)d_in[9];
    float* out = (float*)d_out;

    bf16 *wqcTh, *wqcTl, *wkTh, *wkTl, *wvTh, *wvTl, *woTh, *woTl;
    bf16 *xhi, *xlo, *yhi, *ylo;
    float *bqc, *qc, *kb, *vb, *yb;
    cudaGetSymbolAddress((void**)&wqcTh, g_WqcT_hi);
    cudaGetSymbolAddress((void**)&wqcTl, g_WqcT_lo);
    cudaGetSymbolAddress((void**)&wkTh,  g_WkT_hi);
    cudaGetSymbolAddress((void**)&wkTl,  g_WkT_lo);
    cudaGetSymbolAddress((void**)&wvTh,  g_WvT_hi);
    cudaGetSymbolAddress((void**)&wvTl,  g_WvT_lo);
    cudaGetSymbolAddress((void**)&woTh,  g_WoT_hi);
    cudaGetSymbolAddress((void**)&woTl,  g_WoT_lo);
    cudaGetSymbolAddress((void**)&xhi,   g_xhi);
    cudaGetSymbolAddress((void**)&xlo,   g_xlo);
    cudaGetSymbolAddress((void**)&yhi,   g_yhi);
    cudaGetSymbolAddress((void**)&ylo,   g_ylo);
    cudaGetSymbolAddress((void**)&bqc,   g_bqc);
    cudaGetSymbolAddress((void**)&qc,    g_qc);
    cudaGetSymbolAddress((void**)&kb,    g_k);
    cudaGetSymbolAddress((void**)&vb,    g_v);
    cudaGetSymbolAddress((void**)&yb,    g_y);

    cudaFuncSetAttribute(flash_attn,
                         cudaFuncAttributeMaxDynamicSharedMemorySize,
                         FLASH_SMEM);
    cudaFuncSetAttribute(sgemm_tc,
                         cudaFuncAttributeMaxDynamicSharedMemorySize,
                         TC_SMEM);

    prep_wqc<<<(CDIM*CDIM)/256, 256>>>(Wq, Wc);
    prep_bqc<<<CDIM/256, 256>>>(bq, Wc);
    conv_wT<<<(CDIM*CDIM)/256, 256>>>(Wk, wkTh, wkTl);
    conv_wT<<<(CDIM*CDIM)/256, 256>>>(Wv, wvTh, wvTl);
    conv_wT<<<(CDIM*CDIM)/256, 256>>>(Wo, woTh, woTl);
    conv_split<<<(MROWS*CDIM)/256, 256>>>(x, xhi, xlo);

    dim3 gg(CDIM/128, MROWS/128);   // (8, 32)
    sgemm_tc<<<gg, 256, TC_SMEM>>>(xhi, xlo, wqcTh, wqcTl, bqc, qc);
    sgemm_tc<<<gg, 256, TC_SMEM>>>(xhi, xlo, wkTh,  wkTl,  bk,  kb);
    sgemm_tc<<<gg, 256, TC_SMEM>>>(xhi, xlo, wvTh,  wvTl,  bv,  vb);

    flash_attn<<<dim3(TDIM/128, BDIM*HN), 256, FLASH_SMEM>>>(qc, kb, vb, yb);

    conv_split<<<(MROWS*CDIM)/256, 256>>>(yb, yhi, ylo);
    sgemm_tc<<<gg, 256, TC_SMEM>>>(yhi, ylo, woTh, woTl, bo, out);
}